// round 2
// baseline (speedup 1.0000x reference)
#include <cuda_runtime.h>
#include <cstdint>
#include <math.h>

#define TOK 8192
#define DIM 2048
#define DHID 1024
#define DOUT 1024

// ---- scratch (allocation-free: __device__ globals) ----
__device__ float g_q[(size_t)TOK * DHID];
__device__ float g_k[(size_t)TOK * DHID];
__device__ float g_v[(size_t)TOK * DHID];
__device__ float g_s[(size_t)TOK * TOK];       // 256 MB scores / softmax in-place
__device__ float g_ctx[(size_t)TOK * DHID];

// ============================================================================
// NT GEMM: C[M,Nc] = A[M,K] * B[Nc,K]^T (+ bias[Nc]) (+ res[M,Nc])
// A, B row-major with K contiguous. All dims multiples of 128 (K mult of 8).
// 128x128 block tile, BK=8, 8x8 per thread, 256 threads.
// ============================================================================
template<bool BIAS, bool RES>
__global__ void __launch_bounds__(256, 2)
gemm_nt(const float* __restrict__ A, const float* __restrict__ B,
        const float* __restrict__ bias, const float* __restrict__ res,
        float* __restrict__ C, int M, int Nc, int K)
{
    __shared__ float As[8][128];
    __shared__ float Bs[8][128];

    const int bm = blockIdx.y << 7;
    const int bn = blockIdx.x << 7;
    const int tid = threadIdx.x;
    const int tm = (tid >> 4) << 3;     // 0..120
    const int tn = (tid & 15) << 3;     // 0..120
    const int lr = tid >> 1;            // 0..127 (tile row for loads)
    const int lc = (tid & 1) << 2;      // 0 or 4 (k offset for loads)

    const float* Aptr = A + (size_t)(bm + lr) * K + lc;
    const float* Bptr = B + (size_t)(bn + lr) * K + lc;

    float acc[8][8];
    #pragma unroll
    for (int i = 0; i < 8; i++)
        #pragma unroll
        for (int j = 0; j < 8; j++) acc[i][j] = 0.0f;

    for (int k0 = 0; k0 < K; k0 += 8) {
        float4 a4 = *(const float4*)(Aptr + k0);
        float4 b4 = *(const float4*)(Bptr + k0);
        As[lc + 0][lr] = a4.x; As[lc + 1][lr] = a4.y;
        As[lc + 2][lr] = a4.z; As[lc + 3][lr] = a4.w;
        Bs[lc + 0][lr] = b4.x; Bs[lc + 1][lr] = b4.y;
        Bs[lc + 2][lr] = b4.z; Bs[lc + 3][lr] = b4.w;
        __syncthreads();

        #pragma unroll
        for (int kk = 0; kk < 8; kk++) {
            float4 a0 = *(const float4*)&As[kk][tm];
            float4 a1 = *(const float4*)&As[kk][tm + 4];
            float4 b0 = *(const float4*)&Bs[kk][tn];
            float4 b1 = *(const float4*)&Bs[kk][tn + 4];
            float ar[8] = {a0.x, a0.y, a0.z, a0.w, a1.x, a1.y, a1.z, a1.w};
            float br[8] = {b0.x, b0.y, b0.z, b0.w, b1.x, b1.y, b1.z, b1.w};
            #pragma unroll
            for (int i = 0; i < 8; i++)
                #pragma unroll
                for (int j = 0; j < 8; j++)
                    acc[i][j] = fmaf(ar[i], br[j], acc[i][j]);
        }
        __syncthreads();
    }

    float4 bia0, bia1;
    if (BIAS) {
        bia0 = *(const float4*)(bias + bn + tn);
        bia1 = *(const float4*)(bias + bn + tn + 4);
    }
    #pragma unroll
    for (int i = 0; i < 8; i++) {
        size_t off = (size_t)(bm + tm + i) * Nc + bn + tn;
        float4 o0 = make_float4(acc[i][0], acc[i][1], acc[i][2], acc[i][3]);
        float4 o1 = make_float4(acc[i][4], acc[i][5], acc[i][6], acc[i][7]);
        if (BIAS) {
            o0.x += bia0.x; o0.y += bia0.y; o0.z += bia0.z; o0.w += bia0.w;
            o1.x += bia1.x; o1.y += bia1.y; o1.z += bia1.z; o1.w += bia1.w;
        }
        if (RES) {
            float4 r0 = *(const float4*)(res + off);
            float4 r1 = *(const float4*)(res + off + 4);
            o0.x += r0.x; o0.y += r0.y; o0.z += r0.z; o0.w += r0.w;
            o1.x += r1.x; o1.y += r1.y; o1.z += r1.z; o1.w += r1.w;
        }
        *(float4*)(C + off)     = o0;
        *(float4*)(C + off + 4) = o1;
    }
}

// ============================================================================
// NN GEMM: C[M,Nc] = A[M,K] * B[K,Nc]  (both row-major, no epilogue extras)
// ============================================================================
__global__ void __launch_bounds__(256, 2)
gemm_nn(const float* __restrict__ A, const float* __restrict__ B,
        float* __restrict__ C, int M, int Nc, int K)
{
    __shared__ float As[8][128];
    __shared__ float Bs[8][128];

    const int bm = blockIdx.y << 7;
    const int bn = blockIdx.x << 7;
    const int tid = threadIdx.x;
    const int tm = (tid >> 4) << 3;
    const int tn = (tid & 15) << 3;
    const int alr = tid >> 1;           // 0..127
    const int alc = (tid & 1) << 2;     // 0 or 4
    const int blr = tid >> 5;           // 0..7
    const int blc = (tid & 31) << 2;    // 0..124

    const float* Aptr = A + (size_t)(bm + alr) * K + alc;
    const float* Bptr = B + (size_t)blr * Nc + bn + blc;

    float acc[8][8];
    #pragma unroll
    for (int i = 0; i < 8; i++)
        #pragma unroll
        for (int j = 0; j < 8; j++) acc[i][j] = 0.0f;

    for (int k0 = 0; k0 < K; k0 += 8) {
        float4 a4 = *(const float4*)(Aptr + k0);
        float4 b4 = *(const float4*)(Bptr + (size_t)k0 * Nc);
        As[alc + 0][alr] = a4.x; As[alc + 1][alr] = a4.y;
        As[alc + 2][alr] = a4.z; As[alc + 3][alr] = a4.w;
        *(float4*)&Bs[blr][blc] = b4;
        __syncthreads();

        #pragma unroll
        for (int kk = 0; kk < 8; kk++) {
            float4 a0 = *(const float4*)&As[kk][tm];
            float4 a1 = *(const float4*)&As[kk][tm + 4];
            float4 b0 = *(const float4*)&Bs[kk][tn];
            float4 b1 = *(const float4*)&Bs[kk][tn + 4];
            float ar[8] = {a0.x, a0.y, a0.z, a0.w, a1.x, a1.y, a1.z, a1.w};
            float br[8] = {b0.x, b0.y, b0.z, b0.w, b1.x, b1.y, b1.z, b1.w};
            #pragma unroll
            for (int i = 0; i < 8; i++)
                #pragma unroll
                for (int j = 0; j < 8; j++)
                    acc[i][j] = fmaf(ar[i], br[j], acc[i][j]);
        }
        __syncthreads();
    }

    #pragma unroll
    for (int i = 0; i < 8; i++) {
        size_t off = (size_t)(bm + tm + i) * Nc + bn + tn;
        *(float4*)(C + off)     = make_float4(acc[i][0], acc[i][1], acc[i][2], acc[i][3]);
        *(float4*)(C + off + 4) = make_float4(acc[i][4], acc[i][5], acc[i][6], acc[i][7]);
    }
}

// ============================================================================
// Row softmax, in place. One block per row, 256 threads, 32 elems/thread.
// ============================================================================
__global__ void __launch_bounds__(256)
softmax_rows(float* __restrict__ S, int n)
{
    __shared__ float red[8];
    float* p = S + (size_t)blockIdx.x * n;
    const int tid = threadIdx.x;
    const int lane = tid & 31;
    const int warp = tid >> 5;

    float4 vals[8];
    float lmax = -INFINITY;
    #pragma unroll
    for (int i = 0; i < 8; i++) {
        vals[i] = *(const float4*)(p + ((i << 8) + tid) * 4);
        lmax = fmaxf(lmax, fmaxf(fmaxf(vals[i].x, vals[i].y), fmaxf(vals[i].z, vals[i].w)));
    }
    #pragma unroll
    for (int o = 16; o > 0; o >>= 1)
        lmax = fmaxf(lmax, __shfl_xor_sync(0xffffffffu, lmax, o));
    if (lane == 0) red[warp] = lmax;
    __syncthreads();
    float rmax = red[0];
    #pragma unroll
    for (int w = 1; w < 8; w++) rmax = fmaxf(rmax, red[w]);
    __syncthreads();

    float lsum = 0.0f;
    #pragma unroll
    for (int i = 0; i < 8; i++) {
        vals[i].x = expf(vals[i].x - rmax);
        vals[i].y = expf(vals[i].y - rmax);
        vals[i].z = expf(vals[i].z - rmax);
        vals[i].w = expf(vals[i].w - rmax);
        lsum += (vals[i].x + vals[i].y) + (vals[i].z + vals[i].w);
    }
    #pragma unroll
    for (int o = 16; o > 0; o >>= 1)
        lsum += __shfl_xor_sync(0xffffffffu, lsum, o);
    if (lane == 0) red[warp] = lsum;
    __syncthreads();
    float rsum = 0.0f;
    #pragma unroll
    for (int w = 0; w < 8; w++) rsum += red[w];
    float inv = 1.0f / rsum;

    #pragma unroll
    for (int i = 0; i < 8; i++) {
        vals[i].x *= inv; vals[i].y *= inv; vals[i].z *= inv; vals[i].w *= inv;
        *(float4*)(p + ((i << 8) + tid) * 4) = vals[i];
    }
}

// ============================================================================
// Launch
// ============================================================================
extern "C" void kernel_launch(void* const* d_in, const int* in_sizes, int n_in,
                              void* d_out, int out_size)
{
    const float* O0   = (const float*)d_in[0];
    const float* Ww   = (const float*)d_in[1];
    const float* Wb   = (const float*)d_in[2];
    const float* Uw   = (const float*)d_in[3];
    const float* Ub   = (const float*)d_in[4];
    const float* Hw   = (const float*)d_in[5];
    const float* Hb   = (const float*)d_in[6];
    const float* fc0w = (const float*)d_in[7];
    const float* fc0b = (const float*)d_in[8];
    const float* fc1w = (const float*)d_in[9];
    const float* fc1b = (const float*)d_in[10];

    float* O1 = (float*)d_out;
    float* O2 = O1 + (size_t)TOK * DIM;

    float *q, *k, *v, *s, *ctx;
    cudaGetSymbolAddress((void**)&q,   g_q);
    cudaGetSymbolAddress((void**)&k,   g_k);
    cudaGetSymbolAddress((void**)&v,   g_v);
    cudaGetSymbolAddress((void**)&s,   g_s);
    cudaGetSymbolAddress((void**)&ctx, g_ctx);

    dim3 blk(256);

    // q/k/v projections: [8192,2048] @ [1024,2048]^T + bias
    dim3 gqkv(DHID / 128, TOK / 128);
    gemm_nt<true, false><<<gqkv, blk>>>(O0, Ww, Wb, nullptr, q, TOK, DHID, DIM);
    gemm_nt<true, false><<<gqkv, blk>>>(O0, Uw, Ub, nullptr, k, TOK, DHID, DIM);
    gemm_nt<true, false><<<gqkv, blk>>>(O0, Hw, Hb, nullptr, v, TOK, DHID, DIM);

    // scores = q @ k^T  [8192, 8192], K=1024
    dim3 gsc(TOK / 128, TOK / 128);
    gemm_nt<false, false><<<gsc, blk>>>(q, k, nullptr, nullptr, s, TOK, TOK, DHID);

    // softmax rows, in place
    softmax_rows<<<TOK, 256>>>(s, TOK);

    // ctx = softmax @ v   [8192, 1024], K=8192  (NN)
    gemm_nn<<<dim3(DHID / 128, TOK / 128), blk>>>(s, v, ctx, TOK, DHID, TOK);

    // O1 = O0 + ctx @ fc0w^T + fc0b   [8192, 2048], K=1024
    gemm_nt<true, true><<<dim3(DIM / 128, TOK / 128), blk>>>(ctx, fc0w, fc0b, O0, O1, TOK, DIM, DHID);

    // O2 = O1 @ fc1w^T + fc1b   [8192, 1024], K=2048
    gemm_nt<true, false><<<dim3(DOUT / 128, TOK / 128), blk>>>(O1, fc1w, fc1b, nullptr, O2, TOK, DOUT, DIM);
}

// round 4
// speedup vs baseline: 2.9329x; 2.9329x over previous
#include <cuda_runtime.h>
#include <cuda_bf16.h>
#include <cstdint>
#include <math.h>

#define TOK 8192
#define DIM 2048
#define DHID 1024
#define DOUT 1024

// ---------------------------------------------------------------------------
// Scratch (__device__ globals; allocation-free per harness rules)
// ---------------------------------------------------------------------------
__device__ __align__(256) float g_s[(size_t)TOK * TOK];             // fp32 scores

__device__ __align__(256) __nv_bfloat16 g_O0h[(size_t)TOK * DIM];
__device__ __align__(256) __nv_bfloat16 g_O0l[(size_t)TOK * DIM];
__device__ __align__(256) __nv_bfloat16 g_Wwh[(size_t)DHID * DIM];
__device__ __align__(256) __nv_bfloat16 g_Wwl[(size_t)DHID * DIM];
__device__ __align__(256) __nv_bfloat16 g_Uwh[(size_t)DHID * DIM];
__device__ __align__(256) __nv_bfloat16 g_Uwl[(size_t)DHID * DIM];
__device__ __align__(256) __nv_bfloat16 g_Hwh[(size_t)DHID * DIM];
__device__ __align__(256) __nv_bfloat16 g_Hwl[(size_t)DHID * DIM];
__device__ __align__(256) __nv_bfloat16 g_qh[(size_t)TOK * DHID];
__device__ __align__(256) __nv_bfloat16 g_ql[(size_t)TOK * DHID];
__device__ __align__(256) __nv_bfloat16 g_kh[(size_t)TOK * DHID];
__device__ __align__(256) __nv_bfloat16 g_kl[(size_t)TOK * DHID];
__device__ __align__(256) __nv_bfloat16 g_vTh[(size_t)DHID * TOK];
__device__ __align__(256) __nv_bfloat16 g_vTl[(size_t)DHID * TOK];
__device__ __align__(256) __nv_bfloat16 g_Sh[(size_t)TOK * TOK];
__device__ __align__(256) __nv_bfloat16 g_Sl[(size_t)TOK * TOK];
__device__ __align__(256) __nv_bfloat16 g_ch[(size_t)TOK * DHID];
__device__ __align__(256) __nv_bfloat16 g_cl[(size_t)TOK * DHID];
__device__ __align__(256) __nv_bfloat16 g_f0h[(size_t)DIM * DHID];
__device__ __align__(256) __nv_bfloat16 g_f0l[(size_t)DIM * DHID];
__device__ __align__(256) __nv_bfloat16 g_O1h[(size_t)TOK * DIM];
__device__ __align__(256) __nv_bfloat16 g_O1l[(size_t)TOK * DIM];
__device__ __align__(256) __nv_bfloat16 g_f1h[(size_t)DOUT * DIM];
__device__ __align__(256) __nv_bfloat16 g_f1l[(size_t)DOUT * DIM];

// ---------------------------------------------------------------------------
// helpers
// ---------------------------------------------------------------------------
__device__ __forceinline__ uint32_t smem_to_u32(const void* p) {
    uint32_t a;
    asm("{ .reg .u64 t; cvta.to.shared.u64 t, %1; cvt.u32.u64 %0, t; }" : "=r"(a) : "l"(p));
    return a;
}
#define SWZ128(o) ((o) ^ (((o) >> 3) & 0x70))

__device__ __forceinline__ void ldmatrix4(uint32_t* r, uint32_t addr) {
    asm volatile("ldmatrix.sync.aligned.m8n8.x4.shared.b16 {%0,%1,%2,%3}, [%4];"
                 : "=r"(r[0]), "=r"(r[1]), "=r"(r[2]), "=r"(r[3]) : "r"(addr));
}
__device__ __forceinline__ void mma16816(float* c, const uint32_t* a, const uint32_t* b) {
    asm volatile("mma.sync.aligned.m16n8k16.row.col.f32.bf16.bf16.f32 "
                 "{%0,%1,%2,%3}, {%4,%5,%6,%7}, {%8,%9}, {%0,%1,%2,%3};"
                 : "+f"(c[0]), "+f"(c[1]), "+f"(c[2]), "+f"(c[3])
                 : "r"(a[0]), "r"(a[1]), "r"(a[2]), "r"(a[3]), "r"(b[0]), "r"(b[1]));
}
__device__ __forceinline__ void cp_async16(uint32_t dst, const void* src) {
    asm volatile("cp.async.cg.shared.global [%0], [%1], 16;" :: "r"(dst), "l"(src));
}
#define CP_COMMIT()  asm volatile("cp.async.commit_group;" ::: "memory")
#define CP_WAIT1()   asm volatile("cp.async.wait_group 1;" ::: "memory")

__device__ __forceinline__ void pair_store(__nv_bfloat16* __restrict__ hi,
                                           __nv_bfloat16* __restrict__ lo,
                                           size_t idx, float v) {
    __nv_bfloat16 h = __float2bfloat16(v);
    hi[idx] = h;
    lo[idx] = __float2bfloat16(v - __bfloat162float(h));
}

// ---------------------------------------------------------------------------
// GEMM NT: C[M,N] = pair(A)[M,K] * pair(B)[N,K]^T (+bias)(+res)
// 128x128 CTA tile, BK=32. Smem row layout per tile row: [hi 64B | lo 64B],
// SW128 swizzled. 8 warps as 2(m) x 4(n); warp tile 64x32.
// 3 HMMA products per frag pair: hi*hi + hi*lo + lo*hi.
// 3-stage cp.async pipeline (32KB/stage).
// ---------------------------------------------------------------------------
#define STAGE_BYTES 32768
#define SM_BYTES (3 * STAGE_BYTES)

template<bool COLBIAS, bool ROWBIAS, bool RES, bool OUTF, bool OUTP>
__global__ void __launch_bounds__(256)
gemm_pair(const __nv_bfloat16* __restrict__ Ahi, const __nv_bfloat16* __restrict__ Alo,
          const __nv_bfloat16* __restrict__ Bhi, const __nv_bfloat16* __restrict__ Blo,
          const float* __restrict__ bias, const float* __restrict__ res,
          float* __restrict__ Cf,
          __nv_bfloat16* __restrict__ Chi, __nv_bfloat16* __restrict__ Clo,
          int M, int N, int K)
{
    extern __shared__ char smem[];
    const uint32_t smem_base = smem_to_u32(smem);
    const int tid  = threadIdx.x;
    const int wid  = tid >> 5;
    const int lane = tid & 31;
    const int wm   = wid >> 2;        // 0..1
    const int wn   = wid & 3;         // 0..3
    const int bm = blockIdx.y << 7;
    const int bn = blockIdx.x << 7;

    float acc[4][4][4];
    #pragma unroll
    for (int i = 0; i < 4; i++)
        #pragma unroll
        for (int j = 0; j < 4; j++)
            #pragma unroll
            for (int e = 0; e < 4; e++) acc[i][j][e] = 0.0f;

    const int NCH = K >> 5;           // K/32 chunks

    auto load_chunk = [&](int kk, int slot) {
        const uint32_t sbase = smem_base + slot * STAGE_BYTES;
        #pragma unroll
        for (int it = 0; it < 8; it++) {
            int id   = it * 256 + tid;
            int tile = id >> 10;          // 0 = A, 1 = B
            int id2  = id & 1023;
            int row  = id2 >> 3;
            int rem  = id2 & 7;
            int hl   = rem >> 2;          // 0 = hi, 1 = lo
            int kc   = rem & 3;           // 16B chunk within 64B half
            uint32_t cb  = (uint32_t)(hl * 64 + kc * 16);
            uint32_t dst = sbase + (tile ? 16384u : 0u)
                         + SWZ128((uint32_t)(row << 7) + cb);
            const __nv_bfloat16* src;
            if (tile == 0) src = (hl ? Alo : Ahi) + (size_t)(bm + row) * K;
            else           src = (hl ? Blo : Bhi) + (size_t)(bn + row) * K;
            cp_async16(dst, src + ((size_t)kk << 5) + kc * 8);
        }
    };

    load_chunk(0, 0); CP_COMMIT();
    load_chunk(1, 1); CP_COMMIT();

    // ldmatrix address components (constant across chunks)
    const int arow0 = (wm << 6) + (lane & 15);          // A: m row
    const uint32_t acol = (uint32_t)((lane >> 4) << 4); // A: 16B k-half select
    const int brow0 = (wn << 5) + ((lane >> 4) << 3) + (lane & 7);
    const uint32_t bcol = (uint32_t)(((lane >> 3) & 1) << 4);

    for (int c = 0; c < NCH; c++) {
        CP_WAIT1();
        __syncthreads();
        const uint32_t sbase = smem_base + (c % 3) * STAGE_BYTES;
        const uint32_t Abase = sbase;
        const uint32_t Bbase = sbase + 16384u;

        #pragma unroll
        for (int ks = 0; ks < 2; ks++) {
            uint32_t Ah[4][4], Al[4][4], Bh[2][4], Bl[2][4];
            const uint32_t kb = (uint32_t)(ks << 5);
            #pragma unroll
            for (int f = 0; f < 4; f++) {
                uint32_t ro = (uint32_t)((arow0 + (f << 4)) << 7);
                ldmatrix4(Ah[f], Abase + SWZ128(ro + kb + acol));
                ldmatrix4(Al[f], Abase + SWZ128(ro + kb + acol + 64u));
            }
            #pragma unroll
            for (int g = 0; g < 2; g++) {
                uint32_t ro = (uint32_t)((brow0 + (g << 4)) << 7);
                ldmatrix4(Bh[g], Bbase + SWZ128(ro + kb + bcol));
                ldmatrix4(Bl[g], Bbase + SWZ128(ro + kb + bcol + 64u));
            }
            #pragma unroll
            for (int mf = 0; mf < 4; mf++) {
                #pragma unroll
                for (int nf = 0; nf < 4; nf++) {
                    const int g = nf >> 1, h = (nf & 1) << 1;
                    mma16816(acc[mf][nf], Ah[mf], &Bh[g][h]);   // hi*hi
                    mma16816(acc[mf][nf], Ah[mf], &Bl[g][h]);   // hi*lo
                    mma16816(acc[mf][nf], Al[mf], &Bh[g][h]);   // lo*hi
                }
            }
        }
        if (c + 2 < NCH) load_chunk(c + 2, (c + 2) % 3);
        CP_COMMIT();
    }

    // ------------------------- epilogue -------------------------
    const int qrow = lane >> 2;           // 0..7
    const int qcol = (lane & 3) << 1;     // 0,2,4,6
    #pragma unroll
    for (int mf = 0; mf < 4; mf++) {
        #pragma unroll
        for (int half = 0; half < 2; half++) {
            const int r = bm + (wm << 6) + (mf << 4) + qrow + (half << 3);
            float rb = 0.0f;
            if (ROWBIAS) rb = bias[r];
            #pragma unroll
            for (int nf = 0; nf < 4; nf++) {
                const int col = bn + (wn << 5) + (nf << 3) + qcol;
                const size_t idx = (size_t)r * N + col;
                float v0 = acc[mf][nf][half * 2 + 0];
                float v1 = acc[mf][nf][half * 2 + 1];
                if (COLBIAS) { v0 += bias[col]; v1 += bias[col + 1]; }
                if (ROWBIAS) { v0 += rb; v1 += rb; }
                if (RES)     { v0 += res[idx]; v1 += res[idx + 1]; }
                if (OUTF)    { *(float2*)(Cf + idx) = make_float2(v0, v1); }
                if (OUTP) {
                    pair_store(Chi, Clo, idx,     v0);
                    pair_store(Chi, Clo, idx + 1, v1);
                }
            }
        }
    }
}

// ---------------------------------------------------------------------------
// fp32 -> (hi, lo) bf16 split conversion
// ---------------------------------------------------------------------------
__global__ void __launch_bounds__(256)
pairify(const float4* __restrict__ src, __nv_bfloat16* __restrict__ hi,
        __nv_bfloat16* __restrict__ lo, int n4)
{
    int i = blockIdx.x * blockDim.x + threadIdx.x;
    if (i >= n4) return;
    float4 v = src[i];
    size_t b = (size_t)i * 4;
    pair_store(hi, lo, b + 0, v.x);
    pair_store(hi, lo, b + 1, v.y);
    pair_store(hi, lo, b + 2, v.z);
    pair_store(hi, lo, b + 3, v.w);
}

// ---------------------------------------------------------------------------
// Row softmax: fp32 scores in, (hi, lo) bf16 split weights out
// ---------------------------------------------------------------------------
__global__ void __launch_bounds__(256)
softmax_pair(const float* __restrict__ S, __nv_bfloat16* __restrict__ Wh,
             __nv_bfloat16* __restrict__ Wl)
{
    __shared__ float red[8];
    const size_t rowbase = (size_t)blockIdx.x * TOK;
    const float* p = S + rowbase;
    const int tid = threadIdx.x;
    const int lane = tid & 31;
    const int warp = tid >> 5;

    float4 vals[8];
    float lmax = -INFINITY;
    #pragma unroll
    for (int i = 0; i < 8; i++) {
        vals[i] = *(const float4*)(p + ((i << 8) + tid) * 4);
        lmax = fmaxf(lmax, fmaxf(fmaxf(vals[i].x, vals[i].y), fmaxf(vals[i].z, vals[i].w)));
    }
    #pragma unroll
    for (int o = 16; o > 0; o >>= 1)
        lmax = fmaxf(lmax, __shfl_xor_sync(0xffffffffu, lmax, o));
    if (lane == 0) red[warp] = lmax;
    __syncthreads();
    float rmax = red[0];
    #pragma unroll
    for (int w = 1; w < 8; w++) rmax = fmaxf(rmax, red[w]);
    __syncthreads();

    float lsum = 0.0f;
    #pragma unroll
    for (int i = 0; i < 8; i++) {
        vals[i].x = expf(vals[i].x - rmax);
        vals[i].y = expf(vals[i].y - rmax);
        vals[i].z = expf(vals[i].z - rmax);
        vals[i].w = expf(vals[i].w - rmax);
        lsum += (vals[i].x + vals[i].y) + (vals[i].z + vals[i].w);
    }
    #pragma unroll
    for (int o = 16; o > 0; o >>= 1)
        lsum += __shfl_xor_sync(0xffffffffu, lsum, o);
    if (lane == 0) red[warp] = lsum;
    __syncthreads();
    float rsum = 0.0f;
    #pragma unroll
    for (int w = 0; w < 8; w++) rsum += red[w];
    const float inv = 1.0f / rsum;

    #pragma unroll
    for (int i = 0; i < 8; i++) {
        const size_t b = rowbase + ((i << 8) + tid) * 4;
        pair_store(Wh, Wl, b + 0, vals[i].x * inv);
        pair_store(Wh, Wl, b + 1, vals[i].y * inv);
        pair_store(Wh, Wl, b + 2, vals[i].z * inv);
        pair_store(Wh, Wl, b + 3, vals[i].w * inv);
    }
}

// ---------------------------------------------------------------------------
// Launch
// ---------------------------------------------------------------------------
template<bool CB, bool RB, bool RE, bool OF, bool OP>
static void set_smem_attr() {
    cudaFuncSetAttribute(gemm_pair<CB, RB, RE, OF, OP>,
                         cudaFuncAttributeMaxDynamicSharedMemorySize, SM_BYTES);
}

extern "C" void kernel_launch(void* const* d_in, const int* in_sizes, int n_in,
                              void* d_out, int out_size)
{
    const float* O0   = (const float*)d_in[0];
    const float* Ww   = (const float*)d_in[1];
    const float* Wb   = (const float*)d_in[2];
    const float* Uw   = (const float*)d_in[3];
    const float* Ub   = (const float*)d_in[4];
    const float* Hw   = (const float*)d_in[5];
    const float* Hb   = (const float*)d_in[6];
    const float* fc0w = (const float*)d_in[7];
    const float* fc0b = (const float*)d_in[8];
    const float* fc1w = (const float*)d_in[9];
    const float* fc1b = (const float*)d_in[10];

    float* O1 = (float*)d_out;
    float* O2 = O1 + (size_t)TOK * DIM;

    set_smem_attr<true,  false, false, false, true >();  // q, k
    set_smem_attr<false, true,  false, false, true >();  // vT
    set_smem_attr<false, false, false, true,  false>();  // scores
    set_smem_attr<false, false, false, false, true >();  // ctx
    set_smem_attr<true,  false, true,  true,  true >();  // fc0
    set_smem_attr<true,  false, false, true,  false>();  // fc1

    float* s;
    __nv_bfloat16 *O0h, *O0l, *Wwh, *Wwl, *Uwh, *Uwl, *Hwh, *Hwl;
    __nv_bfloat16 *qh, *ql, *kh, *kl, *vTh, *vTl, *Sh, *Sl, *ch, *cl;
    __nv_bfloat16 *f0h, *f0l, *O1h, *O1l, *f1h, *f1l;
    cudaGetSymbolAddress((void**)&s,   g_s);
    cudaGetSymbolAddress((void**)&O0h, g_O0h); cudaGetSymbolAddress((void**)&O0l, g_O0l);
    cudaGetSymbolAddress((void**)&Wwh, g_Wwh); cudaGetSymbolAddress((void**)&Wwl, g_Wwl);
    cudaGetSymbolAddress((void**)&Uwh, g_Uwh); cudaGetSymbolAddress((void**)&Uwl, g_Uwl);
    cudaGetSymbolAddress((void**)&Hwh, g_Hwh); cudaGetSymbolAddress((void**)&Hwl, g_Hwl);
    cudaGetSymbolAddress((void**)&qh,  g_qh);  cudaGetSymbolAddress((void**)&ql,  g_ql);
    cudaGetSymbolAddress((void**)&kh,  g_kh);  cudaGetSymbolAddress((void**)&kl,  g_kl);
    cudaGetSymbolAddress((void**)&vTh, g_vTh); cudaGetSymbolAddress((void**)&vTl, g_vTl);
    cudaGetSymbolAddress((void**)&Sh,  g_Sh);  cudaGetSymbolAddress((void**)&Sl,  g_Sl);
    cudaGetSymbolAddress((void**)&ch,  g_ch);  cudaGetSymbolAddress((void**)&cl,  g_cl);
    cudaGetSymbolAddress((void**)&f0h, g_f0h); cudaGetSymbolAddress((void**)&f0l, g_f0l);
    cudaGetSymbolAddress((void**)&O1h, g_O1h); cudaGetSymbolAddress((void**)&O1l, g_O1l);
    cudaGetSymbolAddress((void**)&f1h, g_f1h); cudaGetSymbolAddress((void**)&f1l, g_f1l);

    auto cvt = [](const float* src, __nv_bfloat16* hi, __nv_bfloat16* lo, size_t n) {
        int n4 = (int)(n / 4);
        pairify<<<(n4 + 255) / 256, 256>>>((const float4*)src, hi, lo, n4);
    };
    cvt(O0,   O0h, O0l, (size_t)TOK * DIM);
    cvt(Ww,   Wwh, Wwl, (size_t)DHID * DIM);
    cvt(Uw,   Uwh, Uwl, (size_t)DHID * DIM);
    cvt(Hw,   Hwh, Hwl, (size_t)DHID * DIM);
    cvt(fc0w, f0h, f0l, (size_t)DIM * DHID);
    cvt(fc1w, f1h, f1l, (size_t)DOUT * DIM);

    // q = O0 @ Ww^T + Wb           [8192, 1024]
    gemm_pair<true, false, false, false, true><<<dim3(DHID / 128, TOK / 128), 256, SM_BYTES>>>(
        O0h, O0l, Wwh, Wwl, Wb, nullptr, nullptr, qh, ql, TOK, DHID, DIM);
    // k = O0 @ Uw^T + Ub
    gemm_pair<true, false, false, false, true><<<dim3(DHID / 128, TOK / 128), 256, SM_BYTES>>>(
        O0h, O0l, Uwh, Uwl, Ub, nullptr, nullptr, kh, kl, TOK, DHID, DIM);
    // vT = Hw @ O0^T + Hb (row-bias)  [1024, 8192]
    gemm_pair<false, true, false, false, true><<<dim3(TOK / 128, DHID / 128), 256, SM_BYTES>>>(
        Hwh, Hwl, O0h, O0l, Hb, nullptr, nullptr, vTh, vTl, DHID, TOK, DIM);
    // scores = q @ k^T (fp32 out)   [8192, 8192]
    gemm_pair<false, false, false, true, false><<<dim3(TOK / 128, TOK / 128), 256, SM_BYTES>>>(
        qh, ql, kh, kl, nullptr, nullptr, s, nullptr, nullptr, TOK, TOK, DHID);
    // softmax -> split weights
    softmax_pair<<<TOK, 256>>>(s, Sh, Sl);
    // ctx = softmax @ v = Spair @ vT^T   [8192, 1024]
    gemm_pair<false, false, false, false, true><<<dim3(DHID / 128, TOK / 128), 256, SM_BYTES>>>(
        Sh, Sl, vTh, vTl, nullptr, nullptr, nullptr, ch, cl, TOK, DHID, TOK);
    // O1 = O0 + ctx @ fc0w^T + fc0b  (fp32 + pair out)  [8192, 2048]
    gemm_pair<true, false, true, true, true><<<dim3(DIM / 128, TOK / 128), 256, SM_BYTES>>>(
        ch, cl, f0h, f0l, fc0b, O0, O1, O1h, O1l, TOK, DIM, DHID);
    // O2 = O1 @ fc1w^T + fc1b  (fp32 out)  [8192, 1024]
    gemm_pair<true, false, false, true, false><<<dim3(DOUT / 128, TOK / 128), 256, SM_BYTES>>>(
        O1h, O1l, f1h, f1l, fc1b, nullptr, O2, nullptr, nullptr, TOK, DOUT, DIM);
}

// round 5
// speedup vs baseline: 3.1324x; 1.0680x over previous
#include <cuda_runtime.h>
#include <cuda_bf16.h>
#include <cstdint>
#include <math.h>

#define TOK 8192
#define DIM 2048
#define DHID 1024
#define DOUT 1024

// ---------------------------------------------------------------------------
// Scratch (__device__ globals; allocation-free per harness rules)
// ---------------------------------------------------------------------------
__device__ __align__(256) float g_s[(size_t)TOK * TOK];             // fp32 scores

__device__ __align__(256) __nv_bfloat16 g_O0h[(size_t)TOK * DIM];
__device__ __align__(256) __nv_bfloat16 g_O0l[(size_t)TOK * DIM];
__device__ __align__(256) __nv_bfloat16 g_Wwh[(size_t)DHID * DIM];
__device__ __align__(256) __nv_bfloat16 g_Wwl[(size_t)DHID * DIM];
__device__ __align__(256) __nv_bfloat16 g_Uwh[(size_t)DHID * DIM];
__device__ __align__(256) __nv_bfloat16 g_Uwl[(size_t)DHID * DIM];
__device__ __align__(256) __nv_bfloat16 g_Hwh[(size_t)DHID * DIM];
__device__ __align__(256) __nv_bfloat16 g_Hwl[(size_t)DHID * DIM];
__device__ __align__(256) __nv_bfloat16 g_qh[(size_t)TOK * DHID];
__device__ __align__(256) __nv_bfloat16 g_ql[(size_t)TOK * DHID];
__device__ __align__(256) __nv_bfloat16 g_kh[(size_t)TOK * DHID];
__device__ __align__(256) __nv_bfloat16 g_kl[(size_t)TOK * DHID];
__device__ __align__(256) __nv_bfloat16 g_vTh[(size_t)DHID * TOK];
__device__ __align__(256) __nv_bfloat16 g_vTl[(size_t)DHID * TOK];
__device__ __align__(256) __nv_bfloat16 g_Sh[(size_t)TOK * TOK];
__device__ __align__(256) __nv_bfloat16 g_Sl[(size_t)TOK * TOK];
__device__ __align__(256) __nv_bfloat16 g_ch[(size_t)TOK * DHID];
__device__ __align__(256) __nv_bfloat16 g_cl[(size_t)TOK * DHID];
__device__ __align__(256) __nv_bfloat16 g_f0h[(size_t)DIM * DHID];
__device__ __align__(256) __nv_bfloat16 g_f0l[(size_t)DIM * DHID];
__device__ __align__(256) __nv_bfloat16 g_O1h[(size_t)TOK * DIM];
__device__ __align__(256) __nv_bfloat16 g_O1l[(size_t)TOK * DIM];
__device__ __align__(256) __nv_bfloat16 g_f1h[(size_t)DOUT * DIM];
__device__ __align__(256) __nv_bfloat16 g_f1l[(size_t)DOUT * DIM];

// ---------------------------------------------------------------------------
// helpers
// ---------------------------------------------------------------------------
__device__ __forceinline__ uint32_t smem_to_u32(const void* p) {
    uint32_t a;
    asm("{ .reg .u64 t; cvta.to.shared.u64 t, %1; cvt.u32.u64 %0, t; }" : "=r"(a) : "l"(p));
    return a;
}
#define SWZ128(o) ((o) ^ (((o) >> 3) & 0x70))

__device__ __forceinline__ void ldmatrix4(uint32_t* r, uint32_t addr) {
    asm volatile("ldmatrix.sync.aligned.m8n8.x4.shared.b16 {%0,%1,%2,%3}, [%4];"
                 : "=r"(r[0]), "=r"(r[1]), "=r"(r[2]), "=r"(r[3]) : "r"(addr));
}
__device__ __forceinline__ void mma16816(float* c, const uint32_t* a, const uint32_t* b) {
    asm volatile("mma.sync.aligned.m16n8k16.row.col.f32.bf16.bf16.f32 "
                 "{%0,%1,%2,%3}, {%4,%5,%6,%7}, {%8,%9}, {%0,%1,%2,%3};"
                 : "+f"(c[0]), "+f"(c[1]), "+f"(c[2]), "+f"(c[3])
                 : "r"(a[0]), "r"(a[1]), "r"(a[2]), "r"(a[3]), "r"(b[0]), "r"(b[1]));
}
__device__ __forceinline__ void cp_async16(uint32_t dst, const void* src) {
    asm volatile("cp.async.cg.shared.global [%0], [%1], 16;" :: "r"(dst), "l"(src));
}
#define CP_COMMIT()  asm volatile("cp.async.commit_group;" ::: "memory")
#define CP_WAIT1()   asm volatile("cp.async.wait_group 1;" ::: "memory")

__device__ __forceinline__ void pair_store(__nv_bfloat16* __restrict__ hi,
                                           __nv_bfloat16* __restrict__ lo,
                                           size_t idx, float v) {
    __nv_bfloat16 h = __float2bfloat16(v);
    hi[idx] = h;
    lo[idx] = __float2bfloat16(v - __bfloat162float(h));
}

// ---------------------------------------------------------------------------
// GEMM NT: C[M,N] = pair(A)[M,K] * pair(B)[N,K]^T (+bias)(+res)
// CTA tile 128x256, BK=32. Smem row layout: [hi 64B | lo 64B], SW128.
// 8 warps as 2(m) x 4(n); warp tile 64x64.
// 3 HMMA sweeps per frag pair: hi*hi + lo*hi + hi*lo (frag regs sequenced).
// 3-stage cp.async pipeline (48KB/stage).
// ---------------------------------------------------------------------------
#define STAGE_BYTES 49152
#define SM_BYTES (3 * STAGE_BYTES)

template<bool COLBIAS, bool ROWBIAS, bool RES, bool OUTF, bool OUTP>
__global__ void __launch_bounds__(256, 1)
gemm_pair(const __nv_bfloat16* __restrict__ Ahi, const __nv_bfloat16* __restrict__ Alo,
          const __nv_bfloat16* __restrict__ Bhi, const __nv_bfloat16* __restrict__ Blo,
          const float* __restrict__ bias, const float* __restrict__ res,
          float* __restrict__ Cf,
          __nv_bfloat16* __restrict__ Chi, __nv_bfloat16* __restrict__ Clo,
          int M, int N, int K)
{
    extern __shared__ char smem[];
    const uint32_t smem_base = smem_to_u32(smem);
    const int tid  = threadIdx.x;
    const int wid  = tid >> 5;
    const int lane = tid & 31;
    const int wm   = wid >> 2;        // 0..1  (m 64-row half)
    const int wn   = wid & 3;         // 0..3  (n 64-col quarter)
    const int bm = blockIdx.y << 7;
    const int bn = blockIdx.x << 8;

    float acc[4][8][4];
    #pragma unroll
    for (int i = 0; i < 4; i++)
        #pragma unroll
        for (int j = 0; j < 8; j++)
            #pragma unroll
            for (int e = 0; e < 4; e++) acc[i][j][e] = 0.0f;

    const int NCH = K >> 5;           // K/32 chunks

    // stage layout: A 128 rows x 128B at +0 (16KB), B 256 rows x 128B at +16KB
    auto load_chunk = [&](int kk, int slot) {
        const uint32_t sbase = smem_base + slot * STAGE_BYTES;
        #pragma unroll
        for (int it = 0; it < 12; it++) {
            int id  = it * 256 + tid;         // 0..3071 16B-chunks
            int isB = id >= 1024;
            int id2 = isB ? id - 1024 : id;
            int row = id2 >> 3;
            int rem = id2 & 7;
            int hl  = rem >> 2;               // 0 = hi, 1 = lo
            int kc  = rem & 3;                // 16B piece within 64B half
            uint32_t cb  = (uint32_t)(hl * 64 + kc * 16);
            uint32_t dst = sbase + (isB ? 16384u : 0u)
                         + SWZ128((uint32_t)(row << 7) + cb);
            const __nv_bfloat16* src;
            if (isB) src = (hl ? Blo : Bhi) + (size_t)(bn + row) * K;
            else     src = (hl ? Alo : Ahi) + (size_t)(bm + row) * K;
            cp_async16(dst, src + ((size_t)kk << 5) + kc * 8);
        }
    };

    load_chunk(0, 0); CP_COMMIT();
    load_chunk(1, 1); CP_COMMIT();

    // ldmatrix address components (constant across chunks)
    const int arow0 = (wm << 6) + (lane & 15);          // A m-row within tile
    const uint32_t acol = (uint32_t)((lane >> 4) << 4); // A 16B k-half select
    const int brow0 = (wn << 6) + ((lane >> 4) << 3) + (lane & 7);
    const uint32_t bcol = (uint32_t)(((lane >> 3) & 1) << 4);

    for (int c = 0; c < NCH; c++) {
        CP_WAIT1();
        __syncthreads();
        const uint32_t sbase = smem_base + (c % 3) * STAGE_BYTES;
        const uint32_t Abase = sbase;
        const uint32_t Bbase = sbase + 16384u;

        #pragma unroll
        for (int ks = 0; ks < 2; ks++) {
            const uint32_t kb = (uint32_t)(ks << 5);
            uint32_t Ah[4][4], Ax[4][4], Bf[4][4];
            // hi fragments
            #pragma unroll
            for (int f = 0; f < 4; f++) {
                uint32_t ro = (uint32_t)((arow0 + (f << 4)) << 7);
                ldmatrix4(Ah[f], Abase + SWZ128(ro + kb + acol));
            }
            #pragma unroll
            for (int g = 0; g < 4; g++) {
                uint32_t ro = (uint32_t)((brow0 + (g << 4)) << 7);
                ldmatrix4(Bf[g], Bbase + SWZ128(ro + kb + bcol));
            }
            // hi * hi
            #pragma unroll
            for (int mf = 0; mf < 4; mf++)
                #pragma unroll
                for (int nf = 0; nf < 8; nf++)
                    mma16816(acc[mf][nf], Ah[mf], &Bf[nf >> 1][(nf & 1) << 1]);
            // lo(A) * hi(B)
            #pragma unroll
            for (int f = 0; f < 4; f++) {
                uint32_t ro = (uint32_t)((arow0 + (f << 4)) << 7);
                ldmatrix4(Ax[f], Abase + SWZ128(ro + kb + acol + 64u));
            }
            #pragma unroll
            for (int mf = 0; mf < 4; mf++)
                #pragma unroll
                for (int nf = 0; nf < 8; nf++)
                    mma16816(acc[mf][nf], Ax[mf], &Bf[nf >> 1][(nf & 1) << 1]);
            // hi(A) * lo(B)  (overwrite B frags with lo)
            #pragma unroll
            for (int g = 0; g < 4; g++) {
                uint32_t ro = (uint32_t)((brow0 + (g << 4)) << 7);
                ldmatrix4(Bf[g], Bbase + SWZ128(ro + kb + bcol + 64u));
            }
            #pragma unroll
            for (int mf = 0; mf < 4; mf++)
                #pragma unroll
                for (int nf = 0; nf < 8; nf++)
                    mma16816(acc[mf][nf], Ah[mf], &Bf[nf >> 1][(nf & 1) << 1]);
        }
        if (c + 2 < NCH) load_chunk(c + 2, (c + 2) % 3);
        CP_COMMIT();
    }

    // ------------------------- epilogue -------------------------
    const int qrow = lane >> 2;           // 0..7
    const int qcol = (lane & 3) << 1;     // 0,2,4,6
    #pragma unroll
    for (int mf = 0; mf < 4; mf++) {
        #pragma unroll
        for (int half = 0; half < 2; half++) {
            const int r = bm + (wm << 6) + (mf << 4) + qrow + (half << 3);
            float rb = 0.0f;
            if (ROWBIAS) rb = bias[r];
            #pragma unroll
            for (int nf = 0; nf < 8; nf++) {
                const int col = bn + (wn << 6) + (nf << 3) + qcol;
                const size_t idx = (size_t)r * N + col;
                float v0 = acc[mf][nf][half * 2 + 0];
                float v1 = acc[mf][nf][half * 2 + 1];
                if (COLBIAS) { v0 += bias[col]; v1 += bias[col + 1]; }
                if (ROWBIAS) { v0 += rb; v1 += rb; }
                if (RES)     { v0 += res[idx]; v1 += res[idx + 1]; }
                if (OUTF)    { *(float2*)(Cf + idx) = make_float2(v0, v1); }
                if (OUTP) {
                    pair_store(Chi, Clo, idx,     v0);
                    pair_store(Chi, Clo, idx + 1, v1);
                }
            }
        }
    }
}

// ---------------------------------------------------------------------------
// fp32 -> (hi, lo) bf16 split conversion
// ---------------------------------------------------------------------------
__global__ void __launch_bounds__(256)
pairify(const float4* __restrict__ src, __nv_bfloat16* __restrict__ hi,
        __nv_bfloat16* __restrict__ lo, int n4)
{
    int i = blockIdx.x * blockDim.x + threadIdx.x;
    if (i >= n4) return;
    float4 v = src[i];
    size_t b = (size_t)i * 4;
    pair_store(hi, lo, b + 0, v.x);
    pair_store(hi, lo, b + 1, v.y);
    pair_store(hi, lo, b + 2, v.z);
    pair_store(hi, lo, b + 3, v.w);
}

// ---------------------------------------------------------------------------
// Row softmax: fp32 scores in, (hi, lo) bf16 split weights out
// ---------------------------------------------------------------------------
__global__ void __launch_bounds__(256)
softmax_pair(const float* __restrict__ S, __nv_bfloat16* __restrict__ Wh,
             __nv_bfloat16* __restrict__ Wl)
{
    __shared__ float red[8];
    const size_t rowbase = (size_t)blockIdx.x * TOK;
    const float* p = S + rowbase;
    const int tid = threadIdx.x;
    const int lane = tid & 31;
    const int warp = tid >> 5;

    float4 vals[8];
    float lmax = -INFINITY;
    #pragma unroll
    for (int i = 0; i < 8; i++) {
        vals[i] = *(const float4*)(p + ((i << 8) + tid) * 4);
        lmax = fmaxf(lmax, fmaxf(fmaxf(vals[i].x, vals[i].y), fmaxf(vals[i].z, vals[i].w)));
    }
    #pragma unroll
    for (int o = 16; o > 0; o >>= 1)
        lmax = fmaxf(lmax, __shfl_xor_sync(0xffffffffu, lmax, o));
    if (lane == 0) red[warp] = lmax;
    __syncthreads();
    float rmax = red[0];
    #pragma unroll
    for (int w = 1; w < 8; w++) rmax = fmaxf(rmax, red[w]);
    __syncthreads();

    float lsum = 0.0f;
    #pragma unroll
    for (int i = 0; i < 8; i++) {
        vals[i].x = expf(vals[i].x - rmax);
        vals[i].y = expf(vals[i].y - rmax);
        vals[i].z = expf(vals[i].z - rmax);
        vals[i].w = expf(vals[i].w - rmax);
        lsum += (vals[i].x + vals[i].y) + (vals[i].z + vals[i].w);
    }
    #pragma unroll
    for (int o = 16; o > 0; o >>= 1)
        lsum += __shfl_xor_sync(0xffffffffu, lsum, o);
    if (lane == 0) red[warp] = lsum;
    __syncthreads();
    float rsum = 0.0f;
    #pragma unroll
    for (int w = 0; w < 8; w++) rsum += red[w];
    const float inv = 1.0f / rsum;

    #pragma unroll
    for (int i = 0; i < 8; i++) {
        const size_t b = rowbase + ((i << 8) + tid) * 4;
        pair_store(Wh, Wl, b + 0, vals[i].x * inv);
        pair_store(Wh, Wl, b + 1, vals[i].y * inv);
        pair_store(Wh, Wl, b + 2, vals[i].z * inv);
        pair_store(Wh, Wl, b + 3, vals[i].w * inv);
    }
}

// ---------------------------------------------------------------------------
// Launch
// ---------------------------------------------------------------------------
template<bool CB, bool RB, bool RE, bool OF, bool OP>
static void set_smem_attr() {
    cudaFuncSetAttribute(gemm_pair<CB, RB, RE, OF, OP>,
                         cudaFuncAttributeMaxDynamicSharedMemorySize, SM_BYTES);
}

extern "C" void kernel_launch(void* const* d_in, const int* in_sizes, int n_in,
                              void* d_out, int out_size)
{
    const float* O0   = (const float*)d_in[0];
    const float* Ww   = (const float*)d_in[1];
    const float* Wb   = (const float*)d_in[2];
    const float* Uw   = (const float*)d_in[3];
    const float* Ub   = (const float*)d_in[4];
    const float* Hw   = (const float*)d_in[5];
    const float* Hb   = (const float*)d_in[6];
    const float* fc0w = (const float*)d_in[7];
    const float* fc0b = (const float*)d_in[8];
    const float* fc1w = (const float*)d_in[9];
    const float* fc1b = (const float*)d_in[10];

    float* O1 = (float*)d_out;
    float* O2 = O1 + (size_t)TOK * DIM;

    set_smem_attr<true,  false, false, false, true >();  // q, k
    set_smem_attr<false, true,  false, false, true >();  // vT
    set_smem_attr<false, false, false, true,  false>();  // scores
    set_smem_attr<false, false, false, false, true >();  // ctx
    set_smem_attr<true,  false, true,  true,  true >();  // fc0
    set_smem_attr<true,  false, false, true,  false>();  // fc1

    float* s;
    __nv_bfloat16 *O0h, *O0l, *Wwh, *Wwl, *Uwh, *Uwl, *Hwh, *Hwl;
    __nv_bfloat16 *qh, *ql, *kh, *kl, *vTh, *vTl, *Sh, *Sl, *ch, *cl;
    __nv_bfloat16 *f0h, *f0l, *O1h, *O1l, *f1h, *f1l;
    cudaGetSymbolAddress((void**)&s,   g_s);
    cudaGetSymbolAddress((void**)&O0h, g_O0h); cudaGetSymbolAddress((void**)&O0l, g_O0l);
    cudaGetSymbolAddress((void**)&Wwh, g_Wwh); cudaGetSymbolAddress((void**)&Wwl, g_Wwl);
    cudaGetSymbolAddress((void**)&Uwh, g_Uwh); cudaGetSymbolAddress((void**)&Uwl, g_Uwl);
    cudaGetSymbolAddress((void**)&Hwh, g_Hwh); cudaGetSymbolAddress((void**)&Hwl, g_Hwl);
    cudaGetSymbolAddress((void**)&qh,  g_qh);  cudaGetSymbolAddress((void**)&ql,  g_ql);
    cudaGetSymbolAddress((void**)&kh,  g_kh);  cudaGetSymbolAddress((void**)&kl,  g_kl);
    cudaGetSymbolAddress((void**)&vTh, g_vTh); cudaGetSymbolAddress((void**)&vTl, g_vTl);
    cudaGetSymbolAddress((void**)&Sh,  g_Sh);  cudaGetSymbolAddress((void**)&Sl,  g_Sl);
    cudaGetSymbolAddress((void**)&ch,  g_ch);  cudaGetSymbolAddress((void**)&cl,  g_cl);
    cudaGetSymbolAddress((void**)&f0h, g_f0h); cudaGetSymbolAddress((void**)&f0l, g_f0l);
    cudaGetSymbolAddress((void**)&O1h, g_O1h); cudaGetSymbolAddress((void**)&O1l, g_O1l);
    cudaGetSymbolAddress((void**)&f1h, g_f1h); cudaGetSymbolAddress((void**)&f1l, g_f1l);

    auto cvt = [](const float* src, __nv_bfloat16* hi, __nv_bfloat16* lo, size_t n) {
        int n4 = (int)(n / 4);
        pairify<<<(n4 + 255) / 256, 256>>>((const float4*)src, hi, lo, n4);
    };
    cvt(O0,   O0h, O0l, (size_t)TOK * DIM);
    cvt(Ww,   Wwh, Wwl, (size_t)DHID * DIM);
    cvt(Uw,   Uwh, Uwl, (size_t)DHID * DIM);
    cvt(Hw,   Hwh, Hwl, (size_t)DHID * DIM);
    cvt(fc0w, f0h, f0l, (size_t)DIM * DHID);
    cvt(fc1w, f1h, f1l, (size_t)DOUT * DIM);

    // q = O0 @ Ww^T + Wb           [8192, 1024]
    gemm_pair<true, false, false, false, true><<<dim3(DHID / 256, TOK / 128), 256, SM_BYTES>>>(
        O0h, O0l, Wwh, Wwl, Wb, nullptr, nullptr, qh, ql, TOK, DHID, DIM);
    // k = O0 @ Uw^T + Ub
    gemm_pair<true, false, false, false, true><<<dim3(DHID / 256, TOK / 128), 256, SM_BYTES>>>(
        O0h, O0l, Uwh, Uwl, Ub, nullptr, nullptr, kh, kl, TOK, DHID, DIM);
    // vT = Hw @ O0^T + Hb (row-bias)  [1024, 8192]
    gemm_pair<false, true, false, false, true><<<dim3(TOK / 256, DHID / 128), 256, SM_BYTES>>>(
        Hwh, Hwl, O0h, O0l, Hb, nullptr, nullptr, vTh, vTl, DHID, TOK, DIM);
    // scores = q @ k^T (fp32 out)   [8192, 8192]
    gemm_pair<false, false, false, true, false><<<dim3(TOK / 256, TOK / 128), 256, SM_BYTES>>>(
        qh, ql, kh, kl, nullptr, nullptr, s, nullptr, nullptr, TOK, TOK, DHID);
    // softmax -> split weights
    softmax_pair<<<TOK, 256>>>(s, Sh, Sl);
    // ctx = softmax @ v = Spair @ vT^T   [8192, 1024]
    gemm_pair<false, false, false, false, true><<<dim3(DHID / 256, TOK / 128), 256, SM_BYTES>>>(
        Sh, Sl, vTh, vTl, nullptr, nullptr, nullptr, ch, cl, TOK, DHID, TOK);
    // O1 = O0 + ctx @ fc0w^T + fc0b  (fp32 + pair out)  [8192, 2048]
    gemm_pair<true, false, true, true, true><<<dim3(DIM / 256, TOK / 128), 256, SM_BYTES>>>(
        ch, cl, f0h, f0l, fc0b, O0, O1, O1h, O1l, TOK, DIM, DHID);
    // O2 = O1 @ fc1w^T + fc1b  (fp32 out)  [8192, 1024]
    gemm_pair<true, false, false, true, false><<<dim3(DOUT / 256, TOK / 128), 256, SM_BYTES>>>(
        O1h, O1l, f1h, f1l, fc1b, nullptr, O2, nullptr, nullptr, TOK, DOUT, DIM);
}

// round 7
// speedup vs baseline: 3.5387x; 1.1297x over previous
#include <cuda_runtime.h>
#include <cuda_fp16.h>
#include <cstdint>
#include <math.h>

#define TOK 8192
#define DIM 2048
#define DHID 1024
#define DOUT 1024

// ---------------------------------------------------------------------------
// Scratch (__device__ globals; allocation-free per harness rules)
// ---------------------------------------------------------------------------
__device__ __align__(256) float g_s[(size_t)TOK * TOK];             // fp32 scores

__device__ __align__(256) __half g_O0h[(size_t)TOK * DIM];
__device__ __align__(256) __half g_O0l[(size_t)TOK * DIM];
__device__ __align__(256) __half g_Wwh[(size_t)DHID * DIM];
__device__ __align__(256) __half g_Wwl[(size_t)DHID * DIM];
__device__ __align__(256) __half g_Uwh[(size_t)DHID * DIM];
__device__ __align__(256) __half g_Uwl[(size_t)DHID * DIM];
__device__ __align__(256) __half g_Hwh[(size_t)DHID * DIM];
__device__ __align__(256) __half g_Hwl[(size_t)DHID * DIM];
__device__ __align__(256) __half g_qh[(size_t)TOK * DHID];
__device__ __align__(256) __half g_ql[(size_t)TOK * DHID];
__device__ __align__(256) __half g_kh[(size_t)TOK * DHID];
__device__ __align__(256) __half g_kl[(size_t)TOK * DHID];
__device__ __align__(256) __half g_vTh[(size_t)DHID * TOK];
__device__ __align__(256) __half g_vTl[(size_t)DHID * TOK];
__device__ __align__(256) __half g_Sh[(size_t)TOK * TOK];
__device__ __align__(256) __half g_Sl[(size_t)TOK * TOK];
__device__ __align__(256) __half g_ch[(size_t)TOK * DHID];
__device__ __align__(256) __half g_cl[(size_t)TOK * DHID];
__device__ __align__(256) __half g_f0h[(size_t)DIM * DHID];
__device__ __align__(256) __half g_f0l[(size_t)DIM * DHID];
__device__ __align__(256) __half g_O1h[(size_t)TOK * DIM];
__device__ __align__(256) __half g_O1l[(size_t)TOK * DIM];
__device__ __align__(256) __half g_f1h[(size_t)DOUT * DIM];
__device__ __align__(256) __half g_f1l[(size_t)DOUT * DIM];

// ---------------------------------------------------------------------------
// helpers
// ---------------------------------------------------------------------------
__device__ __forceinline__ uint32_t smem_to_u32(const void* p) {
    uint32_t a;
    asm("{ .reg .u64 t; cvta.to.shared.u64 t, %1; cvt.u32.u64 %0, t; }" : "=r"(a) : "l"(p));
    return a;
}
#define SWZ128(o) ((o) ^ (((o) >> 3) & 0x70))

__device__ __forceinline__ void ldmatrix4(uint32_t* r, uint32_t addr) {
    asm volatile("ldmatrix.sync.aligned.m8n8.x4.shared.b16 {%0,%1,%2,%3}, [%4];"
                 : "=r"(r[0]), "=r"(r[1]), "=r"(r[2]), "=r"(r[3]) : "r"(addr));
}
__device__ __forceinline__ void mma16816(float* c, const uint32_t* a, const uint32_t* b) {
    asm volatile("mma.sync.aligned.m16n8k16.row.col.f32.f16.f16.f32 "
                 "{%0,%1,%2,%3}, {%4,%5,%6,%7}, {%8,%9}, {%0,%1,%2,%3};"
                 : "+f"(c[0]), "+f"(c[1]), "+f"(c[2]), "+f"(c[3])
                 : "r"(a[0]), "r"(a[1]), "r"(a[2]), "r"(a[3]), "r"(b[0]), "r"(b[1]));
}
__device__ __forceinline__ void cp_async16(uint32_t dst, const void* src) {
    asm volatile("cp.async.cg.shared.global [%0], [%1], 16;" :: "r"(dst), "l"(src));
}
#define CP_COMMIT()  asm volatile("cp.async.commit_group;" ::: "memory")
#define CP_WAIT1()   asm volatile("cp.async.wait_group 1;" ::: "memory")

__device__ __forceinline__ void pair_store(__half* __restrict__ hi,
                                           __half* __restrict__ lo,
                                           size_t idx, float v) {
    __half h = __float2half_rn(v);
    hi[idx] = h;
    lo[idx] = __float2half_rn(v - __half2float(h));
}

// ---------------------------------------------------------------------------
// GEMM NT: C[M,N] = pair(A)[M,K] * pair(B)[N,K]^T (+bias)(+res)
// CTA tile 128x256, BK=32. Smem row layout: [hi 64B | lo 64B], SW128.
// 8 warps as 2(m) x 4(n); warp tile 64x64.
// SWEEPS=3: hi*hi + lo(A)*hi(B) + hi(A)*lo(B)
// SWEEPS=2: hi*hi + lo(A)*hi(B)           (B-lo dropped; fp16 pair precision)
// 3-stage cp.async pipeline (48KB/stage).
// ---------------------------------------------------------------------------
#define STAGE_BYTES 49152
#define SM_BYTES (3 * STAGE_BYTES)

template<int SWEEPS, bool COLBIAS, bool ROWBIAS, bool RES, bool OUTF, bool OUTP>
__global__ void __launch_bounds__(256, 1)
gemm_pair(const __half* __restrict__ Ahi, const __half* __restrict__ Alo,
          const __half* __restrict__ Bhi, const __half* __restrict__ Blo,
          const float* __restrict__ bias, const float* __restrict__ res,
          float* __restrict__ Cf,
          __half* __restrict__ Chi, __half* __restrict__ Clo,
          int M, int N, int K)
{
    extern __shared__ char smem[];
    const uint32_t smem_base = smem_to_u32(smem);
    const int tid  = threadIdx.x;
    const int wid  = tid >> 5;
    const int lane = tid & 31;
    const int wm   = wid >> 2;        // 0..1  (m 64-row half)
    const int wn   = wid & 3;         // 0..3  (n 64-col quarter)
    const int bm = blockIdx.y << 7;
    const int bn = blockIdx.x << 8;

    float acc[4][8][4];
    #pragma unroll
    for (int i = 0; i < 4; i++)
        #pragma unroll
        for (int j = 0; j < 8; j++)
            #pragma unroll
            for (int e = 0; e < 4; e++) acc[i][j][e] = 0.0f;

    const int NCH = K >> 5;           // K/32 chunks

    // stage layout: A 128 rows x 128B at +0 (16KB), B 256 rows x 128B at +16KB
    auto load_chunk = [&](int kk, int slot) {
        const uint32_t sbase = smem_base + slot * STAGE_BYTES;
        #pragma unroll
        for (int it = 0; it < 12; it++) {
            int id  = it * 256 + tid;         // 0..3071 16B-chunks
            int isB = id >= 1024;
            int id2 = isB ? id - 1024 : id;
            int row = id2 >> 3;
            int rem = id2 & 7;
            int hl  = rem >> 2;               // 0 = hi, 1 = lo
            int kc  = rem & 3;                // 16B piece within 64B half
            uint32_t cb  = (uint32_t)(hl * 64 + kc * 16);
            uint32_t dst = sbase + (isB ? 16384u : 0u)
                         + SWZ128((uint32_t)(row << 7) + cb);
            const __half* src;
            if (isB) src = (hl ? Blo : Bhi) + (size_t)(bn + row) * K;
            else     src = (hl ? Alo : Ahi) + (size_t)(bm + row) * K;
            cp_async16(dst, src + ((size_t)kk << 5) + kc * 8);
        }
    };

    load_chunk(0, 0); CP_COMMIT();
    load_chunk(1, 1); CP_COMMIT();

    // ldmatrix address components (constant across chunks)
    const int arow0 = (wm << 6) + (lane & 15);          // A m-row within tile
    const uint32_t acol = (uint32_t)((lane >> 4) << 4); // A 16B k-half select
    const int brow0 = (wn << 6) + ((lane >> 4) << 3) + (lane & 7);
    const uint32_t bcol = (uint32_t)(((lane >> 3) & 1) << 4);

    for (int c = 0; c < NCH; c++) {
        CP_WAIT1();
        __syncthreads();
        const uint32_t sbase = smem_base + (c % 3) * STAGE_BYTES;
        const uint32_t Abase = sbase;
        const uint32_t Bbase = sbase + 16384u;

        #pragma unroll
        for (int ks = 0; ks < 2; ks++) {
            const uint32_t kb = (uint32_t)(ks << 5);
            uint32_t Ah[4][4], Ax[4][4], Bf[4][4];
            // hi fragments
            #pragma unroll
            for (int f = 0; f < 4; f++) {
                uint32_t ro = (uint32_t)((arow0 + (f << 4)) << 7);
                ldmatrix4(Ah[f], Abase + SWZ128(ro + kb + acol));
            }
            #pragma unroll
            for (int g = 0; g < 4; g++) {
                uint32_t ro = (uint32_t)((brow0 + (g << 4)) << 7);
                ldmatrix4(Bf[g], Bbase + SWZ128(ro + kb + bcol));
            }
            // hi * hi
            #pragma unroll
            for (int mf = 0; mf < 4; mf++)
                #pragma unroll
                for (int nf = 0; nf < 8; nf++)
                    mma16816(acc[mf][nf], Ah[mf], &Bf[nf >> 1][(nf & 1) << 1]);
            // lo(A) * hi(B)
            #pragma unroll
            for (int f = 0; f < 4; f++) {
                uint32_t ro = (uint32_t)((arow0 + (f << 4)) << 7);
                ldmatrix4(Ax[f], Abase + SWZ128(ro + kb + acol + 64u));
            }
            #pragma unroll
            for (int mf = 0; mf < 4; mf++)
                #pragma unroll
                for (int nf = 0; nf < 8; nf++)
                    mma16816(acc[mf][nf], Ax[mf], &Bf[nf >> 1][(nf & 1) << 1]);
            if (SWEEPS == 3) {
                // hi(A) * lo(B)  (overwrite B frags with lo)
                #pragma unroll
                for (int g = 0; g < 4; g++) {
                    uint32_t ro = (uint32_t)((brow0 + (g << 4)) << 7);
                    ldmatrix4(Bf[g], Bbase + SWZ128(ro + kb + bcol + 64u));
                }
                #pragma unroll
                for (int mf = 0; mf < 4; mf++)
                    #pragma unroll
                    for (int nf = 0; nf < 8; nf++)
                        mma16816(acc[mf][nf], Ah[mf], &Bf[nf >> 1][(nf & 1) << 1]);
            }
        }
        if (c + 2 < NCH) load_chunk(c + 2, (c + 2) % 3);
        CP_COMMIT();
    }

    // ------------------------- epilogue -------------------------
    const int qrow = lane >> 2;           // 0..7
    const int qcol = (lane & 3) << 1;     // 0,2,4,6
    #pragma unroll
    for (int mf = 0; mf < 4; mf++) {
        #pragma unroll
        for (int half = 0; half < 2; half++) {
            const int r = bm + (wm << 6) + (mf << 4) + qrow + (half << 3);
            float rb = 0.0f;
            if (ROWBIAS) rb = bias[r];
            #pragma unroll
            for (int nf = 0; nf < 8; nf++) {
                const int col = bn + (wn << 6) + (nf << 3) + qcol;
                const size_t idx = (size_t)r * N + col;
                float v0 = acc[mf][nf][half * 2 + 0];
                float v1 = acc[mf][nf][half * 2 + 1];
                if (COLBIAS) { v0 += bias[col]; v1 += bias[col + 1]; }
                if (ROWBIAS) { v0 += rb; v1 += rb; }
                if (RES)     { v0 += res[idx]; v1 += res[idx + 1]; }
                if (OUTF)    { *(float2*)(Cf + idx) = make_float2(v0, v1); }
                if (OUTP) {
                    pair_store(Chi, Clo, idx,     v0);
                    pair_store(Chi, Clo, idx + 1, v1);
                }
            }
        }
    }
}

// ---------------------------------------------------------------------------
// fp32 -> (hi, lo) fp16 split conversion
// ---------------------------------------------------------------------------
__global__ void __launch_bounds__(256)
pairify(const float4* __restrict__ src, __half* __restrict__ hi,
        __half* __restrict__ lo, int n4)
{
    int i = blockIdx.x * blockDim.x + threadIdx.x;
    if (i >= n4) return;
    float4 v = src[i];
    size_t b = (size_t)i * 4;
    pair_store(hi, lo, b + 0, v.x);
    pair_store(hi, lo, b + 1, v.y);
    pair_store(hi, lo, b + 2, v.z);
    pair_store(hi, lo, b + 3, v.w);
}

// ---------------------------------------------------------------------------
// Row softmax: fp32 scores in, (hi, lo) fp16 split weights out
// ---------------------------------------------------------------------------
__global__ void __launch_bounds__(256)
softmax_pair(const float* __restrict__ S, __half* __restrict__ Wh,
             __half* __restrict__ Wl)
{
    __shared__ float red[8];
    const size_t rowbase = (size_t)blockIdx.x * TOK;
    const float* p = S + rowbase;
    const int tid = threadIdx.x;
    const int lane = tid & 31;
    const int warp = tid >> 5;

    float4 vals[8];
    float lmax = -INFINITY;
    #pragma unroll
    for (int i = 0; i < 8; i++) {
        vals[i] = *(const float4*)(p + ((i << 8) + tid) * 4);
        lmax = fmaxf(lmax, fmaxf(fmaxf(vals[i].x, vals[i].y), fmaxf(vals[i].z, vals[i].w)));
    }
    #pragma unroll
    for (int o = 16; o > 0; o >>= 1)
        lmax = fmaxf(lmax, __shfl_xor_sync(0xffffffffu, lmax, o));
    if (lane == 0) red[warp] = lmax;
    __syncthreads();
    float rmax = red[0];
    #pragma unroll
    for (int w = 1; w < 8; w++) rmax = fmaxf(rmax, red[w]);
    __syncthreads();

    float lsum = 0.0f;
    #pragma unroll
    for (int i = 0; i < 8; i++) {
        vals[i].x = expf(vals[i].x - rmax);
        vals[i].y = expf(vals[i].y - rmax);
        vals[i].z = expf(vals[i].z - rmax);
        vals[i].w = expf(vals[i].w - rmax);
        lsum += (vals[i].x + vals[i].y) + (vals[i].z + vals[i].w);
    }
    #pragma unroll
    for (int o = 16; o > 0; o >>= 1)
        lsum += __shfl_xor_sync(0xffffffffu, lsum, o);
    if (lane == 0) red[warp] = lsum;
    __syncthreads();
    float rsum = 0.0f;
    #pragma unroll
    for (int w = 0; w < 8; w++) rsum += red[w];
    const float inv = 1.0f / rsum;

    #pragma unroll
    for (int i = 0; i < 8; i++) {
        const size_t b = rowbase + ((i << 8) + tid) * 4;
        pair_store(Wh, Wl, b + 0, vals[i].x * inv);
        pair_store(Wh, Wl, b + 1, vals[i].y * inv);
        pair_store(Wh, Wl, b + 2, vals[i].z * inv);
        pair_store(Wh, Wl, b + 3, vals[i].w * inv);
    }
}

// ---------------------------------------------------------------------------
// Launch
// ---------------------------------------------------------------------------
template<int SW, bool CB, bool RB, bool RE, bool OF, bool OP>
static void set_smem_attr() {
    cudaFuncSetAttribute(gemm_pair<SW, CB, RB, RE, OF, OP>,
                         cudaFuncAttributeMaxDynamicSharedMemorySize, SM_BYTES);
}

extern "C" void kernel_launch(void* const* d_in, const int* in_sizes, int n_in,
                              void* d_out, int out_size)
{
    const float* O0   = (const float*)d_in[0];
    const float* Ww   = (const float*)d_in[1];
    const float* Wb   = (const float*)d_in[2];
    const float* Uw   = (const float*)d_in[3];
    const float* Ub   = (const float*)d_in[4];
    const float* Hw   = (const float*)d_in[5];
    const float* Hb   = (const float*)d_in[6];
    const float* fc0w = (const float*)d_in[7];
    const float* fc0b = (const float*)d_in[8];
    const float* fc1w = (const float*)d_in[9];
    const float* fc1b = (const float*)d_in[10];

    float* O1 = (float*)d_out;
    float* O2 = O1 + (size_t)TOK * DIM;

    set_smem_attr<3, true,  false, false, false, true >();  // q, k
    set_smem_attr<3, false, true,  false, false, true >();  // vT
    set_smem_attr<3, false, false, false, true,  false>();  // scores
    set_smem_attr<2, false, false, false, false, true >();  // ctx
    set_smem_attr<2, true,  false, true,  true,  true >();  // fc0
    set_smem_attr<2, true,  false, false, true,  false>();  // fc1

    float* s;
    __half *O0h, *O0l, *Wwh, *Wwl, *Uwh, *Uwl, *Hwh, *Hwl;
    __half *qh, *ql, *kh, *kl, *vTh, *vTl, *Sh, *Sl, *ch, *cl;
    __half *f0h, *f0l, *O1h, *O1l, *f1h, *f1l;
    cudaGetSymbolAddress((void**)&s,   g_s);
    cudaGetSymbolAddress((void**)&O0h, g_O0h); cudaGetSymbolAddress((void**)&O0l, g_O0l);
    cudaGetSymbolAddress((void**)&Wwh, g_Wwh); cudaGetSymbolAddress((void**)&Wwl, g_Wwl);
    cudaGetSymbolAddress((void**)&Uwh, g_Uwh); cudaGetSymbolAddress((void**)&Uwl, g_Uwl);
    cudaGetSymbolAddress((void**)&Hwh, g_Hwh); cudaGetSymbolAddress((void**)&Hwl, g_Hwl);
    cudaGetSymbolAddress((void**)&qh,  g_qh);  cudaGetSymbolAddress((void**)&ql,  g_ql);
    cudaGetSymbolAddress((void**)&kh,  g_kh);  cudaGetSymbolAddress((void**)&kl,  g_kl);
    cudaGetSymbolAddress((void**)&vTh, g_vTh); cudaGetSymbolAddress((void**)&vTl, g_vTl);
    cudaGetSymbolAddress((void**)&Sh,  g_Sh);  cudaGetSymbolAddress((void**)&Sl,  g_Sl);
    cudaGetSymbolAddress((void**)&ch,  g_ch);  cudaGetSymbolAddress((void**)&cl,  g_cl);
    cudaGetSymbolAddress((void**)&f0h, g_f0h); cudaGetSymbolAddress((void**)&f0l, g_f0l);
    cudaGetSymbolAddress((void**)&O1h, g_O1h); cudaGetSymbolAddress((void**)&O1l, g_O1l);
    cudaGetSymbolAddress((void**)&f1h, g_f1h); cudaGetSymbolAddress((void**)&f1l, g_f1l);

    auto cvt = [](const float* src, __half* hi, __half* lo, size_t n) {
        int n4 = (int)(n / 4);
        pairify<<<(n4 + 255) / 256, 256>>>((const float4*)src, hi, lo, n4);
    };
    cvt(O0,   O0h, O0l, (size_t)TOK * DIM);
    cvt(Ww,   Wwh, Wwl, (size_t)DHID * DIM);
    cvt(Uw,   Uwh, Uwl, (size_t)DHID * DIM);
    cvt(Hw,   Hwh, Hwl, (size_t)DHID * DIM);
    cvt(fc0w, f0h, f0l, (size_t)DIM * DHID);
    cvt(fc1w, f1h, f1l, (size_t)DOUT * DIM);

    // q = O0 @ Ww^T + Wb           [8192, 1024]   (3 sweeps)
    gemm_pair<3, true, false, false, false, true><<<dim3(DHID / 256, TOK / 128), 256, SM_BYTES>>>(
        O0h, O0l, Wwh, Wwl, Wb, nullptr, nullptr, qh, ql, TOK, DHID, DIM);
    // k = O0 @ Uw^T + Ub           (3 sweeps)
    gemm_pair<3, true, false, false, false, true><<<dim3(DHID / 256, TOK / 128), 256, SM_BYTES>>>(
        O0h, O0l, Uwh, Uwl, Ub, nullptr, nullptr, kh, kl, TOK, DHID, DIM);
    // vT = Hw @ O0^T + Hb (row-bias)  [1024, 8192]  (3 sweeps)
    gemm_pair<3, false, true, false, false, true><<<dim3(TOK / 256, DHID / 128), 256, SM_BYTES>>>(
        Hwh, Hwl, O0h, O0l, Hb, nullptr, nullptr, vTh, vTl, DHID, TOK, DIM);
    // scores = q @ k^T (fp32 out)   [8192, 8192]   (3 sweeps)
    gemm_pair<3, false, false, false, true, false><<<dim3(TOK / 256, TOK / 128), 256, SM_BYTES>>>(
        qh, ql, kh, kl, nullptr, nullptr, s, nullptr, nullptr, TOK, TOK, DHID);
    // softmax -> split weights
    softmax_pair<<<TOK, 256>>>(s, Sh, Sl);
    // ctx = softmax @ v = Spair @ vT^T   [8192, 1024]   (2 sweeps: S corrected, v hi-only)
    gemm_pair<2, false, false, false, false, true><<<dim3(DHID / 256, TOK / 128), 256, SM_BYTES>>>(
        Sh, Sl, vTh, vTl, nullptr, nullptr, nullptr, ch, cl, TOK, DHID, TOK);
    // O1 = O0 + ctx @ fc0w^T + fc0b  (fp32 + pair out)  [8192, 2048]  (2 sweeps)
    gemm_pair<2, true, false, true, true, true><<<dim3(DIM / 256, TOK / 128), 256, SM_BYTES>>>(
        ch, cl, f0h, f0l, fc0b, O0, O1, O1h, O1l, TOK, DIM, DHID);
    // O2 = O1 @ fc1w^T + fc1b  (fp32 out)  [8192, 1024]  (2 sweeps)
    gemm_pair<2, true, false, false, true, false><<<dim3(DOUT / 256, TOK / 128), 256, SM_BYTES>>>(
        O1h, O1l, f1h, f1l, fc1b, nullptr, O2, nullptr, nullptr, TOK, DOUT, DIM);
}